// round 12
// baseline (speedup 1.0000x reference)
#include <cuda_runtime.h>
#include <cuda_bf16.h>
#include <math.h>

#define NN 100000
#define EE 1600000
#define GG 128
#define LL 32
#define HH 64
#define DD 256
#define TNW 16

#define NB   ((NN + 255) / 256)     // 391
#define EB   ((EE + 255) / 256)     // 6250
#define GB   (NN / 16)              // 6250 gather blocks
#define MMB  ((NN + 63) / 64)       // 1563
#define SB   6                      // sub-blocks per graph for pooling

// ---------------- scratch (static device globals; no allocation) -------------
__device__ float         g_f[2 * NN * HH];
__device__ __nv_bfloat16 g_xwb[2 * NN * HH];          // dinv-prescaled xw, bf16
__device__ __nv_bfloat16 g_a[2 * (size_t)NN * DD];    // concat buffer in bf16
__device__ int   g_deg[2 * NN];
__device__ float g_dinv[2 * NN];
__device__ int   g_rowptr[2 * NN];
__device__ int   g_cursor[2 * NN];
__device__ int   g_col[2 * EE];
__device__ int   g_gstart[2 * (GG + 1)];
__device__ float g_sum[2 * GG * DD];
__device__ float g_att[2 * GG * DD];
__device__ float g_t[2 * GG * DD];
__device__ float g_gh[2 * GG * HH];

// ---------------- f32x2 / bf16 helpers ---------------------------------------
__device__ __forceinline__ void fma2(unsigned long long& d, unsigned long long a,
                                     unsigned long long b) {
    asm("fma.rn.f32x2 %0, %1, %2, %0;" : "+l"(d) : "l"(a), "l"(b));
}
__device__ __forceinline__ unsigned long long pack2(float lo, float hi) {
    unsigned long long r;
    asm("mov.b64 %0, {%1, %2};" : "=l"(r) : "f"(lo), "f"(hi));
    return r;
}
__device__ __forceinline__ float2 unpack2(unsigned long long v) {
    float2 r;
    asm("mov.b64 {%0, %1}, %2;" : "=f"(r.x), "=f"(r.y) : "l"(v));
    return r;
}
__device__ __forceinline__ uint2 f4_to_bf4(float4 v) {
    __nv_bfloat162 h0 = __float22bfloat162_rn(make_float2(v.x, v.y));
    __nv_bfloat162 h1 = __float22bfloat162_rn(make_float2(v.z, v.w));
    uint2 u;
    u.x = *reinterpret_cast<unsigned*>(&h0);
    u.y = *reinterpret_cast<unsigned*>(&h1);
    return u;
}
__device__ __forceinline__ float4 f4add(float4 a, float4 b) {
    return make_float4(a.x + b.x, a.y + b.y, a.z + b.z, a.w + b.w);
}

// block-level fused sum-pool: 16 nodes (row) x 16 colquads (cq) hold float4 val.
// part selects which 64-col slice of g_sum. Fast path when block graph-uniform.
__device__ __forceinline__ void block_sum_accum(float4 val, int row, int cq,
                                                int bg, int side, int part,
                                                float4 (*sred)[17], int* sgs) {
    if (cq == 0) sgs[row] = bg;
    sred[row][cq] = val;
    __syncthreads();
    if (sgs[0] == sgs[15]) {
        if (row < 8) sred[row][cq] = f4add(sred[row][cq], sred[row + 8][cq]);
        __syncthreads();
        if (row < 4) sred[row][cq] = f4add(sred[row][cq], sred[row + 4][cq]);
        __syncthreads();
        if (row < 2) sred[row][cq] = f4add(sred[row][cq], sred[row + 2][cq]);
        __syncthreads();
        if (row == 0) {
            float4 s = f4add(sred[0][cq], sred[1][cq]);
            float* dst = &g_sum[side * GG * DD + sgs[0] * DD + part * 64 + cq * 4];
            atomicAdd(dst + 0, s.x); atomicAdd(dst + 1, s.y);
            atomicAdd(dst + 2, s.z); atomicAdd(dst + 3, s.w);
        }
    } else {
        float* dst = &g_sum[side * GG * DD + bg * DD + part * 64 + cq * 4];
        atomicAdd(dst + 0, val.x); atomicAdd(dst + 1, val.y);
        atomicAdd(dst + 2, val.z); atomicAdd(dst + 3, val.w);
    }
}

// gather inner loop: 16-thread group, unweighted sum of xwb rows, 8-deep ILP
__device__ __forceinline__ float4 gather_edges(const uint2* __restrict__ xb,
                                               const int* __restrict__ colp,
                                               int sbase, int cnt, int lane16,
                                               unsigned mask, float4 acc) {
    for (int c = 0; c < cnt; c += 16) {
        int rem = cnt - c;
        int col16 = (lane16 < rem) ? colp[sbase + c + lane16] : 0;
        if (rem >= 16) {
            #pragma unroll 8
            for (int j = 0; j < 16; j++) {
                int col = __shfl_sync(mask, col16, j, 16);
                uint2 u = xb[col * 16 + lane16];
                float2 f0 = __bfloat1622float2(*reinterpret_cast<__nv_bfloat162*>(&u.x));
                float2 f1 = __bfloat1622float2(*reinterpret_cast<__nv_bfloat162*>(&u.y));
                acc.x += f0.x; acc.y += f0.y; acc.z += f1.x; acc.w += f1.y;
            }
        } else {
            for (int j = 0; j < rem; j++) {
                int col = __shfl_sync(mask, col16, j, 16);
                uint2 u = xb[col * 16 + lane16];
                float2 f0 = __bfloat1622float2(*reinterpret_cast<__nv_bfloat162*>(&u.x));
                float2 f1 = __bfloat1622float2(*reinterpret_cast<__nv_bfloat162*>(&u.y));
                acc.x += f0.x; acc.y += f0.y; acc.z += f1.x; acc.w += f1.y;
            }
        }
    }
    return acc;
}

// ---------------- init: zero deg/sum/att + graph start offsets ---------------
__global__ void k_init(const int* __restrict__ b1, const int* __restrict__ b2) {
    int side = blockIdx.y;
    const int* batch = side ? b2 : b1;
    int i = blockIdx.x * 256 + threadIdx.x;
    if (i < NN) {
        g_deg[side * NN + i] = 0;
        int b = batch[i];
        int prev = (i > 0) ? batch[i - 1] : -1;
        for (int g = prev + 1; g <= b; g++) g_gstart[side * (GG + 1) + g] = i;
        if (i == NN - 1)
            for (int g = b + 1; g <= GG; g++) g_gstart[side * (GG + 1) + g] = NN;
    }
    if (i < GG * DD) { g_sum[side * GG * DD + i] = 0.f; g_att[side * GG * DD + i] = 0.f; }
}

__global__ void k_deg(const int* __restrict__ e1, const int* __restrict__ e2) {
    int side = blockIdx.y;
    const int* ei = side ? e2 : e1;
    int e = blockIdx.x * 256 + threadIdx.x;
    if (e < EE) atomicAdd(&g_deg[side * NN + ei[EE + e]], 1);
}

// ---------------- single-block chained scan per side -------------------------
__global__ void __launch_bounds__(1024) k_scan() {
    __shared__ int wsums[32];
    __shared__ int s_carry;
    int side = blockIdx.x;
    int tid = threadIdx.x;
    int lane = tid & 31, wid = tid >> 5;
    if (tid == 0) s_carry = 0;
    __syncthreads();
    for (int base = 0; base < NN; base += 1024) {
        int carry = s_carry;
        int i = base + tid;
        int v = 0;
        if (i < NN) {
            v = g_deg[side * NN + i];
            g_dinv[side * NN + i] = rsqrtf((float)v + 1.f);
        }
        int x = v;
        #pragma unroll
        for (int o = 1; o < 32; o <<= 1) {
            int y = __shfl_up_sync(0xffffffffu, x, o);
            if (lane >= o) x += y;
        }
        if (lane == 31) wsums[wid] = x;
        __syncthreads();
        if (wid == 0) {
            int w = wsums[lane];
            int xx = w;
            #pragma unroll
            for (int o = 1; o < 32; o <<= 1) {
                int y = __shfl_up_sync(0xffffffffu, xx, o);
                if (lane >= o) xx += y;
            }
            wsums[lane] = xx - w;  // exclusive warp offset
        }
        __syncthreads();
        int excl = (x - v) + wsums[wid] + carry;
        if (i < NN) {
            g_rowptr[side * NN + i] = excl;
            g_cursor[side * NN + i] = excl;
        }
        __syncthreads();
        if (tid == 1023) s_carry = carry + wsums[31] + x;
        __syncthreads();
    }
}

// ---- fill: CSR columns only (normalization folded into xwb, no weights) -----
__global__ void k_fill(const int* __restrict__ e1, const int* __restrict__ e2) {
    int side = blockIdx.y;
    const int* ei = side ? e2 : e1;
    int e = blockIdx.x * 256 + threadIdx.x;
    if (e >= EE) return;
    int src = ei[e];
    int dst = ei[EE + e];
    int pos = atomicAdd(&g_cursor[side * NN + dst], 1);
    g_col[side * EE + pos] = src;
}

// -------- pre-layer: f = gsn(features @ preW + b); a[:,0:64]; fused sum ------
__global__ void __launch_bounds__(256) k_pre(const float* __restrict__ ft1,
                                             const float* __restrict__ ft2,
                                             const float* __restrict__ W,
                                             const float* __restrict__ b,
                                             const int* __restrict__ bt1,
                                             const int* __restrict__ bt2,
                                             const float* __restrict__ delta) {
    __shared__ float Ws[LL * HH];
    __shared__ float xs[16 * LL];
    __shared__ float4 sred[16][17];
    __shared__ int sgs[16];
    int side = blockIdx.y;
    const float* feats = side ? ft2 : ft1;
    const int* batch = side ? bt2 : bt1;
    int tid = threadIdx.x;
    int r0 = blockIdx.x * 16;
    float4* Ws4 = (float4*)Ws;
    const float4* Wg = (const float4*)W;
    for (int i = tid; i < LL * HH / 4; i += 256) Ws4[i] = Wg[i];
    float4* xs4 = (float4*)xs;
    const float4* fg = (const float4*)(feats + (size_t)r0 * LL);
    for (int i = tid; i < 16 * (LL / 4); i += 256) xs4[i] = fg[i];
    __syncthreads();
    int row = tid >> 4, cq = tid & 15;
    float4 acc = make_float4(0.f, 0.f, 0.f, 0.f);
    #pragma unroll
    for (int k = 0; k < LL; k++) {
        float xv = xs[row * LL + k];
        float4 w = Ws4[k * 16 + cq];
        acc.x += xv * w.x; acc.y += xv * w.y; acc.z += xv * w.z; acc.w += xv * w.w;
    }
    int n = r0 + row;
    int bg = batch[n];
    float cnt = (float)(g_gstart[side * (GG + 1) + bg + 1] - g_gstart[side * (GG + 1) + bg]);
    float sc = rsqrtf(fmaxf(cnt, 1.f));
    float4 bb = ((const float4*)b)[cq];
    float4 v;
    v.x = (acc.x + bb.x) * sc; v.y = (acc.y + bb.y) * sc;
    v.z = (acc.z + bb.z) * sc; v.w = (acc.w + bb.w) * sc;
    ((float4*)g_f)[(side * NN + n) * 16 + cq] = v;
    float dd = 1.f + delta[0];
    float4 a0;
    a0.x = v.x * dd; a0.y = v.y * dd; a0.z = v.z * dd; a0.w = v.w * dd;
    ((uint2*)g_a)[((size_t)side * NN + n) * 64 + cq] = f4_to_bf4(a0);
    __syncthreads();
    block_sum_accum(a0, row, cq, bg, side, 0, sred, sgs);
}

// -------- mm: xwb = dinv * (f @ W)  (fp32 math, bf16 store) ------------------
__global__ void __launch_bounds__(256) k_mm(const float* __restrict__ W) {
    __shared__ float xs[64 * 64];
    __shared__ float ws[64 * 64];
    int side = blockIdx.y;
    int t = threadIdx.x;
    int r0 = blockIdx.x * 64;
    int nrows = min(64, NN - r0);
    const float4* Wg = (const float4*)W;
    float4* ws4 = (float4*)ws;
    for (int i = t; i < 1024; i += 256) ws4[i] = Wg[i];
    const float4* fg = (const float4*)g_f;
    float4* xs4 = (float4*)xs;
    for (int p = 0; p < 4; p++) {
        int idx = p * 256 + t;
        int r = idx >> 4, kq = idx & 15;
        float4 v = (r < nrows) ? fg[(side * NN + r0 + r) * 16 + kq]
                               : make_float4(0.f, 0.f, 0.f, 0.f);
        xs4[idx] = v;
    }
    __syncthreads();
    int tr = t >> 4, tc = t & 15;
    unsigned long long acc[4][2];
    #pragma unroll
    for (int i = 0; i < 4; i++) { acc[i][0] = 0ull; acc[i][1] = 0ull; }
    const float4* xs4c = (const float4*)xs;
    const float4* ws4c = (const float4*)ws;
    #pragma unroll 4
    for (int k4 = 0; k4 < 16; k4++) {
        float xr[4][4];
        #pragma unroll
        for (int i = 0; i < 4; i++) {
            float4 v = xs4c[(tr * 4 + i) * 16 + k4];
            xr[i][0] = v.x; xr[i][1] = v.y; xr[i][2] = v.z; xr[i][3] = v.w;
        }
        #pragma unroll
        for (int kk = 0; kk < 4; kk++) {
            float4 wv = ws4c[(k4 * 4 + kk) * 16 + tc];
            unsigned long long w01 = pack2(wv.x, wv.y);
            unsigned long long w23 = pack2(wv.z, wv.w);
            #pragma unroll
            for (int i = 0; i < 4; i++) {
                unsigned long long xp = pack2(xr[i][kk], xr[i][kk]);
                fma2(acc[i][0], xp, w01);
                fma2(acc[i][1], xp, w23);
            }
        }
    }
    uint2* xb = (uint2*)g_xwb;
    #pragma unroll
    for (int i = 0; i < 4; i++) {
        int r = r0 + tr * 4 + i;
        if (r >= NN) continue;
        float di = g_dinv[side * NN + r];
        float2 a0 = unpack2(acc[i][0]);
        float2 a1 = unpack2(acc[i][1]);
        xb[(side * NN + r) * 16 + tc] =
            f4_to_bf4(make_float4(a0.x * di, a0.y * di, a1.x * di, a1.y * di));
    }
}

// ------- gather + epilogue + fused sum-pool ----------------------------------
__global__ void __launch_bounds__(256) k_gather(const float* __restrict__ b,
                                                const int* __restrict__ bt1,
                                                const int* __restrict__ bt2,
                                                int layer) {
    __shared__ float4 sred[16][17];
    __shared__ int sgs[16];
    int side = blockIdx.y;
    const int* batch = side ? bt2 : bt1;
    int tid = threadIdx.x;
    int grp = tid >> 4;
    int lane16 = tid & 15;
    int n = blockIdx.x * 16 + grp;
    int s = g_rowptr[side * NN + n];
    int cnt = g_deg[side * NN + n];
    const uint2* xb = (const uint2*)g_xwb + (size_t)side * NN * 16;
    float di = g_dinv[side * NN + n];
    float4 acc;
    {
        uint2 u = xb[n * 16 + lane16];
        float2 f0 = __bfloat1622float2(*reinterpret_cast<__nv_bfloat162*>(&u.x));
        float2 f1 = __bfloat1622float2(*reinterpret_cast<__nv_bfloat162*>(&u.y));
        acc = make_float4(f0.x, f0.y, f1.x, f1.y);
    }
    unsigned mask = 0xFFFFu << (tid & 16);
    const int* colp = g_col + (size_t)side * EE;
    acc = gather_edges(xb, colp, s, cnt, lane16, mask, acc);
    float4 bb = ((const float4*)b)[lane16];
    float4 o;
    o.x = acc.x * di + bb.x; o.y = acc.y * di + bb.y;
    o.z = acc.z * di + bb.z; o.w = acc.w * di + bb.w;
    uint2* ab2 = (uint2*)g_a;
    float4 val;
    if (layer < 2) {
        float4 f = ((float4*)g_f)[(side * NN + n) * 16 + lane16];
        val.x = fmaxf(o.x, 0.f) + f.x; val.y = fmaxf(o.y, 0.f) + f.y;
        val.z = fmaxf(o.z, 0.f) + f.z; val.w = fmaxf(o.w, 0.f) + f.w;
        ((float4*)g_f)[(side * NN + n) * 16 + lane16] = val;
        ab2[((size_t)side * NN + n) * 64 + (layer + 1) * 16 + lane16] = f4_to_bf4(val);
    } else {
        val = o;
        ab2[((size_t)side * NN + n) * 64 + 48 + lane16] = f4_to_bf4(val);
    }
    int bg = batch[n];
    __syncthreads();
    block_sum_accum(val, grp, lane16, bg, side, layer + 1, sred, sgs);
}

// ---------------- ctx = tanh((sum/cnt) @ attW) -------------------------------
__global__ void __launch_bounds__(256) k_ctx(const float* __restrict__ attW) {
    __shared__ float srow[DD];
    int side = blockIdx.y;
    int g = blockIdx.x, tid = threadIdx.x;
    float c = fmaxf((float)(g_gstart[side * (GG + 1) + g + 1] - g_gstart[side * (GG + 1) + g]), 1.f);
    srow[tid] = g_sum[side * GG * DD + g * DD + tid] / c;
    __syncthreads();
    float acc = 0.f;
    for (int k = 0; k < DD; k++) acc += srow[k] * attW[k * DD + tid];
    g_t[side * GG * DD + g * DD + tid] = tanhf(acc);
}

// ---------------- attention pool (bf16 reads, paired rows, fast sigmoid) -----
__device__ __forceinline__ void decode_row(uint4 u, float* v) {
    float2 p0 = __bfloat1622float2(*reinterpret_cast<__nv_bfloat162*>(&u.x));
    float2 p1 = __bfloat1622float2(*reinterpret_cast<__nv_bfloat162*>(&u.y));
    float2 p2 = __bfloat1622float2(*reinterpret_cast<__nv_bfloat162*>(&u.z));
    float2 p3 = __bfloat1622float2(*reinterpret_cast<__nv_bfloat162*>(&u.w));
    v[0] = p0.x; v[1] = p0.y; v[2] = p1.x; v[3] = p1.y;
    v[4] = p2.x; v[5] = p2.y; v[6] = p3.x; v[7] = p3.y;
}

__global__ void __launch_bounds__(256) k_attpool() {
    __shared__ float sm[8 * 256];
    int side = blockIdx.z;
    int g = blockIdx.x;
    int s = g_gstart[side * (GG + 1) + g], e = g_gstart[side * (GG + 1) + g + 1];
    int wid = threadIdx.x >> 5, lane = threadIdx.x & 31;
    int wg = blockIdx.y * 8 + wid;
    const int stride = SB * 8;
    float tval[8];
    #pragma unroll
    for (int j = 0; j < 8; j++) tval[j] = g_t[side * GG * DD + g * DD + lane * 8 + j];
    float acc[8];
    #pragma unroll
    for (int j = 0; j < 8; j++) acc[j] = 0.f;
    const __nv_bfloat16* ab = g_a + (size_t)side * NN * DD;
    int r = s + wg;
    bool lo = (lane < 16);
    for (; r + stride < e; r += 2 * stride) {
        uint4 u0 = ((const uint4*)(ab + (size_t)r * DD))[lane];
        uint4 u1 = ((const uint4*)(ab + (size_t)(r + stride) * DD))[lane];
        float va[8], vb[8];
        decode_row(u0, va);
        decode_row(u1, vb);
        float d0 = 0.f, d1 = 0.f;
        #pragma unroll
        for (int j = 0; j < 8; j++) { d0 += va[j] * tval[j]; d1 += vb[j] * tval[j]; }
        // paired reduction: lo half reduces d0, hi half reduces d1
        float c = lo ? d0 : d1;
        float other = lo ? d1 : d0;
        c += __shfl_xor_sync(0xffffffffu, other, 16);
        #pragma unroll
        for (int o = 8; o; o >>= 1) c += __shfl_xor_sync(0xffffffffu, c, o);
        float coef = __fdividef(1.f, 1.f + __expf(-c));
        float coef0 = __shfl_sync(0xffffffffu, coef, 0);
        float coef1 = __shfl_sync(0xffffffffu, coef, 16);
        #pragma unroll
        for (int j = 0; j < 8; j++) acc[j] += va[j] * coef0 + vb[j] * coef1;
    }
    for (; r < e; r += stride) {
        uint4 u = ((const uint4*)(ab + (size_t)r * DD))[lane];
        float v[8];
        decode_row(u, v);
        float dot = 0.f;
        #pragma unroll
        for (int j = 0; j < 8; j++) dot += v[j] * tval[j];
        #pragma unroll
        for (int o = 16; o; o >>= 1) dot += __shfl_xor_sync(0xffffffffu, dot, o);
        float coef = __fdividef(1.f, 1.f + __expf(-dot));
        #pragma unroll
        for (int j = 0; j < 8; j++) acc[j] += v[j] * coef;
    }
    #pragma unroll
    for (int j = 0; j < 8; j++) sm[wid * 256 + lane * 8 + j] = acc[j];
    __syncthreads();
    int t = threadIdx.x;
    float ssum = 0.f;
    #pragma unroll
    for (int w = 0; w < 8; w++) ssum += sm[w * 256 + t];
    atomicAdd(&g_att[side * GG * DD + g * DD + t], ssum);
}

// ---------------- mix + post-MLP ---------------------------------------------
__global__ void __launch_bounds__(128) k_mlp(const float* __restrict__ mu,
                                             const float* __restrict__ W1, const float* __restrict__ b1,
                                             const float* __restrict__ W2, const float* __restrict__ b2) {
    __shared__ float prow[DD];
    __shared__ float hid[128];
    int side = blockIdx.y;
    int g = blockIdx.x, tid = threadIdx.x;
    {
        int base = side * GG * DD + g * DD;
        float m0 = mu[tid], m1 = mu[tid + 128];
        prow[tid] = m0 * g_att[base + tid] + (1.f - m0) * g_sum[base + tid];
        prow[tid + 128] = m1 * g_att[base + tid + 128] + (1.f - m1) * g_sum[base + tid + 128];
    }
    __syncthreads();
    float h = b1[tid];
    for (int k = 0; k < DD; k++) h += prow[k] * W1[k * 128 + tid];
    hid[tid] = fmaxf(h, 0.f);
    __syncthreads();
    if (tid < HH) {
        float o = b2[tid];
        for (int k = 0; k < 128; k++) o += hid[k] * W2[k * HH + tid];
        g_gh[side * GG * HH + g * HH + tid] = o;
    }
}

// ---------------- final NTN + scoring ----------------------------------------
__global__ void __launch_bounds__(64) k_score(const float* __restrict__ tnW,
                                              const float* __restrict__ tnV,
                                              const float* __restrict__ tnb,
                                              const float* __restrict__ scW1,
                                              const float* __restrict__ scb1,
                                              const float* __restrict__ scW2,
                                              const float* __restrict__ scb2,
                                              const float* __restrict__ alpha,
                                              float* __restrict__ out) {
    __shared__ float gxs[HH], hxs[HH], t1s[TNW], scs[TNW], hid[TNW];
    __shared__ float l2s;
    int g = blockIdx.x, e = threadIdx.x;
    gxs[e] = g_gh[g * HH + e];
    hxs[e] = g_gh[GG * HH + g * HH + e];
    if (e < TNW) t1s[e] = 0.f;
    if (e == 0) l2s = 0.f;
    __syncthreads();
    float acc[TNW];
    #pragma unroll
    for (int k = 0; k < TNW; k++) acc[k] = 0.f;
    for (int d = 0; d < HH; d++) {
        float gd = gxs[d];
        const float4* wp = (const float4*)(tnW + (d * HH + e) * TNW);
        float4 w0 = wp[0], w1 = wp[1], w2 = wp[2], w3 = wp[3];
        acc[0]  += gd * w0.x; acc[1]  += gd * w0.y; acc[2]  += gd * w0.z; acc[3]  += gd * w0.w;
        acc[4]  += gd * w1.x; acc[5]  += gd * w1.y; acc[6]  += gd * w1.z; acc[7]  += gd * w1.w;
        acc[8]  += gd * w2.x; acc[9]  += gd * w2.y; acc[10] += gd * w2.z; acc[11] += gd * w2.w;
        acc[12] += gd * w3.x; acc[13] += gd * w3.y; acc[14] += gd * w3.z; acc[15] += gd * w3.w;
    }
    float hx = hxs[e];
    #pragma unroll
    for (int k = 0; k < TNW; k++) {
        float s = acc[k] * hx;
        #pragma unroll
        for (int o = 16; o; o >>= 1) s += __shfl_xor_sync(0xffffffffu, s, o);
        if ((e & 31) == 0) atomicAdd(&t1s[k], s);
    }
    float df = gxs[e] - hxs[e];
    float s2 = df * df;
    #pragma unroll
    for (int o = 16; o; o >>= 1) s2 += __shfl_xor_sync(0xffffffffu, s2, o);
    if ((e & 31) == 0) atomicAdd(&l2s, s2);
    __syncthreads();
    if (e < TNW) {
        float t2 = tnb[e];
        for (int j = 0; j < HH; j++) t2 += gxs[j] * tnV[e * 2 * HH + j];
        for (int j = 0; j < HH; j++) t2 += hxs[j] * tnV[e * 2 * HH + HH + j];
        scs[e] = fmaxf(t1s[e] + t2, 0.f);
    }
    __syncthreads();
    if (e < TNW) {
        float h = scb1[e];
        for (int j = 0; j < TNW; j++) h += scs[j] * scW1[j * TNW + e];
        hid[e] = fmaxf(h, 0.f);
    }
    __syncthreads();
    if (e == 0) {
        float sc = scb2[0];
        for (int j = 0; j < TNW; j++) sc += hid[j] * scW2[j];
        float l2 = sqrtf(l2s);
        float al = alpha[0];
        out[g] = al * (1.f / (1.f + expf(-sc))) + (1.f - al) * (1.f / (1.f + expf(l2)));
    }
}

// ---------------- launch ------------------------------------------------------
extern "C" void kernel_launch(void* const* d_in, const int* in_sizes, int n_in,
                              void* d_out, int out_size) {
    const int* ei1    = (const int*)d_in[0];
    const int* ei2    = (const int*)d_in[1];
    const int* bt1    = (const int*)d_in[2];
    const int* bt2    = (const int*)d_in[3];
    const float* ft1  = (const float*)d_in[4];
    const float* ft2  = (const float*)d_in[5];
    const float* preW  = (const float*)d_in[6];
    const float* preb  = (const float*)d_in[7];
    const float* convW = (const float*)d_in[8];
    const float* convb = (const float*)d_in[9];
    const float* delta = (const float*)d_in[10];
    const float* alpha = (const float*)d_in[11];
    const float* mu    = (const float*)d_in[12];
    const float* attW  = (const float*)d_in[13];
    const float* pW1   = (const float*)d_in[14];
    const float* pb1   = (const float*)d_in[15];
    const float* pW2   = (const float*)d_in[16];
    const float* pb2   = (const float*)d_in[17];
    const float* tnW   = (const float*)d_in[18];
    const float* tnV   = (const float*)d_in[19];
    const float* tnb   = (const float*)d_in[20];
    const float* scW1  = (const float*)d_in[21];
    const float* scb1  = (const float*)d_in[22];
    const float* scW2  = (const float*)d_in[23];
    const float* scb2  = (const float*)d_in[24];
    float* out = (float*)d_out;

    k_init<<<dim3(NB, 2), 256>>>(bt1, bt2);
    k_deg<<<dim3(EB, 2), 256>>>(ei1, ei2);
    k_scan<<<2, 1024>>>();
    k_fill<<<dim3(EB, 2), 256>>>(ei1, ei2);   // profile slot (observed index 3)
    k_pre<<<dim3(GB, 2), 256>>>(ft1, ft2, preW, preb, bt1, bt2, delta);
    for (int i = 0; i < 3; i++) {
        k_mm<<<dim3(MMB, 2), 256>>>(convW + i * HH * HH);
        k_gather<<<dim3(GB, 2), 256>>>(convb + i * HH, bt1, bt2, i);
    }
    k_ctx<<<dim3(GG, 2), 256>>>(attW);
    k_attpool<<<dim3(GG, SB, 2), 256>>>();
    k_mlp<<<dim3(GG, 2), 128>>>(mu, pW1, pb1, pW2, pb2);
    k_score<<<GG, 64>>>(tnW, tnV, tnb, scW1, scb1, scW2, scb2, alpha, out);
}

// round 13
// speedup vs baseline: 1.0396x; 1.0396x over previous
#include <cuda_runtime.h>
#include <cuda_bf16.h>
#include <math.h>

#define NN 100000
#define EE 1600000
#define GG 128
#define LL 32
#define HH 64
#define DD 256
#define TNW 16

#define NB   ((NN + 255) / 256)     // 391
#define EB   ((EE + 255) / 256)     // 6250
#define GB   (NN / 16)              // 6250 gather blocks
#define MMB  ((NN + 63) / 64)       // 1563
#define SB   6                      // sub-blocks per graph for pooling

// ---------------- scratch (static device globals; no allocation) -------------
__device__ float         g_f[2 * NN * HH];
__device__ __nv_bfloat16 g_xwb[2 * NN * HH];          // dinv-prescaled xw, bf16
__device__ __nv_bfloat16 g_a[2 * (size_t)NN * DD];    // concat buffer in bf16
__device__ int   g_deg[2 * NN];
__device__ float g_dinv[2 * NN];
__device__ int   g_rowptr[2 * NN];
__device__ int   g_cursor[2 * NN];
__device__ int   g_bsum[2 * 512];
__device__ int   g_col[2 * EE];
__device__ int   g_gstart[2 * (GG + 1)];
__device__ float g_sum[2 * GG * DD];
__device__ float g_att[2 * GG * DD];
__device__ float g_t[2 * GG * DD];
__device__ float g_gh[2 * GG * HH];

// ---------------- f32x2 / bf16 helpers ---------------------------------------
__device__ __forceinline__ void fma2(unsigned long long& d, unsigned long long a,
                                     unsigned long long b) {
    asm("fma.rn.f32x2 %0, %1, %2, %0;" : "+l"(d) : "l"(a), "l"(b));
}
__device__ __forceinline__ unsigned long long pack2(float lo, float hi) {
    unsigned long long r;
    asm("mov.b64 %0, {%1, %2};" : "=l"(r) : "f"(lo), "f"(hi));
    return r;
}
__device__ __forceinline__ float2 unpack2(unsigned long long v) {
    float2 r;
    asm("mov.b64 {%0, %1}, %2;" : "=f"(r.x), "=f"(r.y) : "l"(v));
    return r;
}
__device__ __forceinline__ uint2 f4_to_bf4(float4 v) {
    __nv_bfloat162 h0 = __float22bfloat162_rn(make_float2(v.x, v.y));
    __nv_bfloat162 h1 = __float22bfloat162_rn(make_float2(v.z, v.w));
    uint2 u;
    u.x = *reinterpret_cast<unsigned*>(&h0);
    u.y = *reinterpret_cast<unsigned*>(&h1);
    return u;
}

// gather inner loop: 16-thread group, unweighted sum of xwb rows, 8-deep ILP
__device__ __forceinline__ float4 gather_edges(const uint2* __restrict__ xb,
                                               const int* __restrict__ colp,
                                               int sbase, int cnt, int lane16,
                                               unsigned mask, float4 acc) {
    for (int c = 0; c < cnt; c += 16) {
        int rem = cnt - c;
        int col16 = (lane16 < rem) ? colp[sbase + c + lane16] : 0;
        if (rem >= 16) {
            #pragma unroll 8
            for (int j = 0; j < 16; j++) {
                int col = __shfl_sync(mask, col16, j, 16);
                uint2 u = xb[col * 16 + lane16];
                float2 f0 = __bfloat1622float2(*reinterpret_cast<__nv_bfloat162*>(&u.x));
                float2 f1 = __bfloat1622float2(*reinterpret_cast<__nv_bfloat162*>(&u.y));
                acc.x += f0.x; acc.y += f0.y; acc.z += f1.x; acc.w += f1.y;
            }
        } else {
            for (int j = 0; j < rem; j++) {
                int col = __shfl_sync(mask, col16, j, 16);
                uint2 u = xb[col * 16 + lane16];
                float2 f0 = __bfloat1622float2(*reinterpret_cast<__nv_bfloat162*>(&u.x));
                float2 f1 = __bfloat1622float2(*reinterpret_cast<__nv_bfloat162*>(&u.y));
                acc.x += f0.x; acc.y += f0.y; acc.z += f1.x; acc.w += f1.y;
            }
        }
    }
    return acc;
}

// ---------------- init: zero deg/sum/att + graph start offsets ---------------
__global__ void k_init(const int* __restrict__ b1, const int* __restrict__ b2) {
    int side = blockIdx.y;
    const int* batch = side ? b2 : b1;
    int i = blockIdx.x * 256 + threadIdx.x;
    if (i < NN) {
        g_deg[side * NN + i] = 0;
        int b = batch[i];
        int prev = (i > 0) ? batch[i - 1] : -1;
        for (int g = prev + 1; g <= b; g++) g_gstart[side * (GG + 1) + g] = i;
        if (i == NN - 1)
            for (int g = b + 1; g <= GG; g++) g_gstart[side * (GG + 1) + g] = NN;
    }
    if (i < GG * DD) { g_sum[side * GG * DD + i] = 0.f; g_att[side * GG * DD + i] = 0.f; }
}

__global__ void k_deg(const int* __restrict__ e1, const int* __restrict__ e2) {
    int side = blockIdx.y;
    const int* ei = side ? e2 : e1;
    int e = blockIdx.x * 256 + threadIdx.x;
    if (e < EE) atomicAdd(&g_deg[side * NN + ei[EE + e]], 1);
}

// ---------------- CSR build: scans + atomic fill -----------------------------
__global__ void k_scan1() {
    __shared__ int wsum[8];
    int side = blockIdx.y;
    int tid = threadIdx.x;
    int i = blockIdx.x * 256 + tid;
    int v = (i < NN) ? g_deg[side * NN + i] : 0;
    if (i < NN) g_dinv[side * NN + i] = rsqrtf((float)v + 1.f);
    int x = v;
    #pragma unroll
    for (int o = 1; o < 32; o <<= 1) {
        int y = __shfl_up_sync(0xffffffffu, x, o);
        if ((tid & 31) >= o) x += y;
    }
    if ((tid & 31) == 31) wsum[tid >> 5] = x;
    __syncthreads();
    if (tid == 0) {
        int run = 0;
        #pragma unroll
        for (int w = 0; w < 8; w++) { int t = wsum[w]; wsum[w] = run; run += t; }
        g_bsum[side * 512 + blockIdx.x] = run;
    }
    __syncthreads();
    if (i < NN) g_rowptr[side * NN + i] = (x - v) + wsum[tid >> 5];
}

__global__ void __launch_bounds__(512) k_scan2() {
    __shared__ int wsum[16];
    int side = blockIdx.x;
    int tid = threadIdx.x;
    int v = (tid < NB) ? g_bsum[side * 512 + tid] : 0;
    int x = v;
    #pragma unroll
    for (int o = 1; o < 32; o <<= 1) {
        int y = __shfl_up_sync(0xffffffffu, x, o);
        if ((tid & 31) >= o) x += y;
    }
    if ((tid & 31) == 31) wsum[tid >> 5] = x;
    __syncthreads();
    if (tid == 0) {
        int run = 0;
        #pragma unroll
        for (int w = 0; w < 16; w++) { int t = wsum[w]; wsum[w] = run; run += t; }
    }
    __syncthreads();
    if (tid < NB) g_bsum[side * 512 + tid] = (x - v) + wsum[tid >> 5];
}

__global__ void k_scan3() {
    int side = blockIdx.y;
    int i = blockIdx.x * 256 + threadIdx.x;
    if (i < NN) {
        int r = g_rowptr[side * NN + i] + g_bsum[side * 512 + (i >> 8)];
        g_rowptr[side * NN + i] = r;
        g_cursor[side * NN + i] = r;
    }
}

// ---- fill: CSR columns only (normalization folded into xwb, no weights) -----
__global__ void k_fill(const int* __restrict__ e1, const int* __restrict__ e2) {
    int side = blockIdx.y;
    const int* ei = side ? e2 : e1;
    int e = blockIdx.x * 256 + threadIdx.x;
    if (e >= EE) return;
    int src = ei[e];
    int dst = ei[EE + e];
    int pos = atomicAdd(&g_cursor[side * NN + dst], 1);
    g_col[side * EE + pos] = src;
}

// ---------------- pre-layer: f = gsn(features @ preW + b); a[:,0:64] ---------
__global__ void __launch_bounds__(256) k_pre(const float* __restrict__ ft1,
                                             const float* __restrict__ ft2,
                                             const float* __restrict__ W,
                                             const float* __restrict__ b,
                                             const int* __restrict__ bt1,
                                             const int* __restrict__ bt2,
                                             const float* __restrict__ delta) {
    __shared__ float Ws[LL * HH];
    __shared__ float xs[16 * LL];
    int side = blockIdx.y;
    const float* feats = side ? ft2 : ft1;
    const int* batch = side ? bt2 : bt1;
    int tid = threadIdx.x;
    int r0 = blockIdx.x * 16;
    float4* Ws4 = (float4*)Ws;
    const float4* Wg = (const float4*)W;
    for (int i = tid; i < LL * HH / 4; i += 256) Ws4[i] = Wg[i];
    float4* xs4 = (float4*)xs;
    const float4* fg = (const float4*)(feats + (size_t)r0 * LL);
    for (int i = tid; i < 16 * (LL / 4); i += 256) xs4[i] = fg[i];
    __syncthreads();
    int row = tid >> 4, cq = tid & 15;
    float4 acc = make_float4(0.f, 0.f, 0.f, 0.f);
    #pragma unroll
    for (int k = 0; k < LL; k++) {
        float xv = xs[row * LL + k];
        float4 w = Ws4[k * 16 + cq];
        acc.x += xv * w.x; acc.y += xv * w.y; acc.z += xv * w.z; acc.w += xv * w.w;
    }
    int n = r0 + row;
    int bg = batch[n];
    float cnt = (float)(g_gstart[side * (GG + 1) + bg + 1] - g_gstart[side * (GG + 1) + bg]);
    float sc = rsqrtf(fmaxf(cnt, 1.f));
    float4 bb = ((const float4*)b)[cq];
    float4 v;
    v.x = (acc.x + bb.x) * sc; v.y = (acc.y + bb.y) * sc;
    v.z = (acc.z + bb.z) * sc; v.w = (acc.w + bb.w) * sc;
    ((float4*)g_f)[(side * NN + n) * 16 + cq] = v;
    float dd = 1.f + delta[0];
    float4 a0;
    a0.x = v.x * dd; a0.y = v.y * dd; a0.z = v.z * dd; a0.w = v.w * dd;
    ((uint2*)g_a)[((size_t)side * NN + n) * 64 + cq] = f4_to_bf4(a0);
}

// -------- mm: xwb = dinv * (f @ W)  (fp32 math, bf16 store) ------------------
__global__ void __launch_bounds__(256) k_mm(const float* __restrict__ W) {
    __shared__ float xs[64 * 64];
    __shared__ float ws[64 * 64];
    int side = blockIdx.y;
    int t = threadIdx.x;
    int r0 = blockIdx.x * 64;
    int nrows = min(64, NN - r0);
    const float4* Wg = (const float4*)W;
    float4* ws4 = (float4*)ws;
    for (int i = t; i < 1024; i += 256) ws4[i] = Wg[i];
    const float4* fg = (const float4*)g_f;
    float4* xs4 = (float4*)xs;
    for (int p = 0; p < 4; p++) {
        int idx = p * 256 + t;
        int r = idx >> 4, kq = idx & 15;
        float4 v = (r < nrows) ? fg[(side * NN + r0 + r) * 16 + kq]
                               : make_float4(0.f, 0.f, 0.f, 0.f);
        xs4[idx] = v;
    }
    __syncthreads();
    int tr = t >> 4, tc = t & 15;
    unsigned long long acc[4][2];
    #pragma unroll
    for (int i = 0; i < 4; i++) { acc[i][0] = 0ull; acc[i][1] = 0ull; }
    const float4* xs4c = (const float4*)xs;
    const float4* ws4c = (const float4*)ws;
    #pragma unroll 4
    for (int k4 = 0; k4 < 16; k4++) {
        float xr[4][4];
        #pragma unroll
        for (int i = 0; i < 4; i++) {
            float4 v = xs4c[(tr * 4 + i) * 16 + k4];
            xr[i][0] = v.x; xr[i][1] = v.y; xr[i][2] = v.z; xr[i][3] = v.w;
        }
        #pragma unroll
        for (int kk = 0; kk < 4; kk++) {
            float4 wv = ws4c[(k4 * 4 + kk) * 16 + tc];
            unsigned long long w01 = pack2(wv.x, wv.y);
            unsigned long long w23 = pack2(wv.z, wv.w);
            #pragma unroll
            for (int i = 0; i < 4; i++) {
                unsigned long long xp = pack2(xr[i][kk], xr[i][kk]);
                fma2(acc[i][0], xp, w01);
                fma2(acc[i][1], xp, w23);
            }
        }
    }
    uint2* xb = (uint2*)g_xwb;
    #pragma unroll
    for (int i = 0; i < 4; i++) {
        int r = r0 + tr * 4 + i;
        if (r >= NN) continue;
        float di = g_dinv[side * NN + r];
        float2 a0 = unpack2(acc[i][0]);
        float2 a1 = unpack2(acc[i][1]);
        xb[(side * NN + r) * 16 + tc] =
            f4_to_bf4(make_float4(a0.x * di, a0.y * di, a1.x * di, a1.y * di));
    }
}

// ------- gather + epilogue: agg = dinv * (xwb[n] + sum xwb[col]); a-part -----
__global__ void __launch_bounds__(256) k_gather(const float* __restrict__ b,
                                                int layer) {
    int side = blockIdx.y;
    int tid = threadIdx.x;
    int grp = tid >> 4;
    int lane16 = tid & 15;
    int n = blockIdx.x * 16 + grp;
    int s = g_rowptr[side * NN + n];
    int cnt = g_deg[side * NN + n];
    const uint2* xb = (const uint2*)g_xwb + (size_t)side * NN * 16;
    float di = g_dinv[side * NN + n];
    float4 acc;
    {
        uint2 u = xb[n * 16 + lane16];
        float2 f0 = __bfloat1622float2(*reinterpret_cast<__nv_bfloat162*>(&u.x));
        float2 f1 = __bfloat1622float2(*reinterpret_cast<__nv_bfloat162*>(&u.y));
        acc = make_float4(f0.x, f0.y, f1.x, f1.y);
    }
    unsigned mask = 0xFFFFu << (tid & 16);
    const int* colp = g_col + (size_t)side * EE;
    acc = gather_edges(xb, colp, s, cnt, lane16, mask, acc);
    float4 bb = ((const float4*)b)[lane16];
    float4 o;
    o.x = acc.x * di + bb.x; o.y = acc.y * di + bb.y;
    o.z = acc.z * di + bb.z; o.w = acc.w * di + bb.w;
    uint2* ab2 = (uint2*)g_a;
    if (layer < 2) {
        float4 f = ((float4*)g_f)[(side * NN + n) * 16 + lane16];
        float4 nf;
        nf.x = fmaxf(o.x, 0.f) + f.x; nf.y = fmaxf(o.y, 0.f) + f.y;
        nf.z = fmaxf(o.z, 0.f) + f.z; nf.w = fmaxf(o.w, 0.f) + f.w;
        ((float4*)g_f)[(side * NN + n) * 16 + lane16] = nf;
        ab2[((size_t)side * NN + n) * 64 + (layer + 1) * 16 + lane16] = f4_to_bf4(nf);
    } else {
        ab2[((size_t)side * NN + n) * 64 + 48 + lane16] = f4_to_bf4(o);
    }
}

// ---------------- sum pool (bf16 reads) --------------------------------------
__global__ void __launch_bounds__(256) k_sumpool() {
    __shared__ float sm[8 * 256];
    int side = blockIdx.z;
    int g = blockIdx.x;
    int s = g_gstart[side * (GG + 1) + g], e = g_gstart[side * (GG + 1) + g + 1];
    int wid = threadIdx.x >> 5, lane = threadIdx.x & 31;
    int wg = blockIdx.y * 8 + wid;
    float acc[8];
    #pragma unroll
    for (int j = 0; j < 8; j++) acc[j] = 0.f;
    const __nv_bfloat16* ab = g_a + (size_t)side * NN * DD;
    for (int r = s + wg; r < e; r += SB * 8) {
        uint4 u = ((const uint4*)(ab + (size_t)r * DD))[lane];
        float2 p0 = __bfloat1622float2(*reinterpret_cast<__nv_bfloat162*>(&u.x));
        float2 p1 = __bfloat1622float2(*reinterpret_cast<__nv_bfloat162*>(&u.y));
        float2 p2 = __bfloat1622float2(*reinterpret_cast<__nv_bfloat162*>(&u.z));
        float2 p3 = __bfloat1622float2(*reinterpret_cast<__nv_bfloat162*>(&u.w));
        acc[0] += p0.x; acc[1] += p0.y; acc[2] += p1.x; acc[3] += p1.y;
        acc[4] += p2.x; acc[5] += p2.y; acc[6] += p3.x; acc[7] += p3.y;
    }
    #pragma unroll
    for (int j = 0; j < 8; j++) sm[wid * 256 + lane * 8 + j] = acc[j];
    __syncthreads();
    int t = threadIdx.x;
    float ssum = 0.f;
    #pragma unroll
    for (int w = 0; w < 8; w++) ssum += sm[w * 256 + t];
    atomicAdd(&g_sum[side * GG * DD + g * DD + t], ssum);
}

// ---------------- ctx = tanh((sum/cnt) @ attW) -------------------------------
__global__ void __launch_bounds__(256) k_ctx(const float* __restrict__ attW) {
    __shared__ float srow[DD];
    int side = blockIdx.y;
    int g = blockIdx.x, tid = threadIdx.x;
    float c = fmaxf((float)(g_gstart[side * (GG + 1) + g + 1] - g_gstart[side * (GG + 1) + g]), 1.f);
    srow[tid] = g_sum[side * GG * DD + g * DD + tid] / c;
    __syncthreads();
    float acc = 0.f;
    for (int k = 0; k < DD; k++) acc += srow[k] * attW[k * DD + tid];
    g_t[side * GG * DD + g * DD + tid] = tanhf(acc);
}

// ---------------- attention pool (bf16 reads, paired rows, fast sigmoid) -----
__device__ __forceinline__ void decode_row(uint4 u, float* v) {
    float2 p0 = __bfloat1622float2(*reinterpret_cast<__nv_bfloat162*>(&u.x));
    float2 p1 = __bfloat1622float2(*reinterpret_cast<__nv_bfloat162*>(&u.y));
    float2 p2 = __bfloat1622float2(*reinterpret_cast<__nv_bfloat162*>(&u.z));
    float2 p3 = __bfloat1622float2(*reinterpret_cast<__nv_bfloat162*>(&u.w));
    v[0] = p0.x; v[1] = p0.y; v[2] = p1.x; v[3] = p1.y;
    v[4] = p2.x; v[5] = p2.y; v[6] = p3.x; v[7] = p3.y;
}

__global__ void __launch_bounds__(256) k_attpool() {
    __shared__ float sm[8 * 256];
    int side = blockIdx.z;
    int g = blockIdx.x;
    int s = g_gstart[side * (GG + 1) + g], e = g_gstart[side * (GG + 1) + g + 1];
    int wid = threadIdx.x >> 5, lane = threadIdx.x & 31;
    int wg = blockIdx.y * 8 + wid;
    const int stride = SB * 8;
    float tval[8];
    #pragma unroll
    for (int j = 0; j < 8; j++) tval[j] = g_t[side * GG * DD + g * DD + lane * 8 + j];
    float acc[8];
    #pragma unroll
    for (int j = 0; j < 8; j++) acc[j] = 0.f;
    const __nv_bfloat16* ab = g_a + (size_t)side * NN * DD;
    int r = s + wg;
    bool lo = (lane < 16);
    for (; r + stride < e; r += 2 * stride) {
        uint4 u0 = ((const uint4*)(ab + (size_t)r * DD))[lane];
        uint4 u1 = ((const uint4*)(ab + (size_t)(r + stride) * DD))[lane];
        float va[8], vb[8];
        decode_row(u0, va);
        decode_row(u1, vb);
        float d0 = 0.f, d1 = 0.f;
        #pragma unroll
        for (int j = 0; j < 8; j++) { d0 += va[j] * tval[j]; d1 += vb[j] * tval[j]; }
        float c = lo ? d0 : d1;
        float other = lo ? d1 : d0;
        c += __shfl_xor_sync(0xffffffffu, other, 16);
        #pragma unroll
        for (int o = 8; o; o >>= 1) c += __shfl_xor_sync(0xffffffffu, c, o);
        float coef = __fdividef(1.f, 1.f + __expf(-c));
        float coef0 = __shfl_sync(0xffffffffu, coef, 0);
        float coef1 = __shfl_sync(0xffffffffu, coef, 16);
        #pragma unroll
        for (int j = 0; j < 8; j++) acc[j] += va[j] * coef0 + vb[j] * coef1;
    }
    for (; r < e; r += stride) {
        uint4 u = ((const uint4*)(ab + (size_t)r * DD))[lane];
        float v[8];
        decode_row(u, v);
        float dot = 0.f;
        #pragma unroll
        for (int j = 0; j < 8; j++) dot += v[j] * tval[j];
        #pragma unroll
        for (int o = 16; o; o >>= 1) dot += __shfl_xor_sync(0xffffffffu, dot, o);
        float coef = __fdividef(1.f, 1.f + __expf(-dot));
        #pragma unroll
        for (int j = 0; j < 8; j++) acc[j] += v[j] * coef;
    }
    #pragma unroll
    for (int j = 0; j < 8; j++) sm[wid * 256 + lane * 8 + j] = acc[j];
    __syncthreads();
    int t = threadIdx.x;
    float ssum = 0.f;
    #pragma unroll
    for (int w = 0; w < 8; w++) ssum += sm[w * 256 + t];
    atomicAdd(&g_att[side * GG * DD + g * DD + t], ssum);
}

// ---------------- mix + post-MLP ---------------------------------------------
__global__ void __launch_bounds__(128) k_mlp(const float* __restrict__ mu,
                                             const float* __restrict__ W1, const float* __restrict__ b1,
                                             const float* __restrict__ W2, const float* __restrict__ b2) {
    __shared__ float prow[DD];
    __shared__ float hid[128];
    int side = blockIdx.y;
    int g = blockIdx.x, tid = threadIdx.x;
    {
        int base = side * GG * DD + g * DD;
        float m0 = mu[tid], m1 = mu[tid + 128];
        prow[tid] = m0 * g_att[base + tid] + (1.f - m0) * g_sum[base + tid];
        prow[tid + 128] = m1 * g_att[base + tid + 128] + (1.f - m1) * g_sum[base + tid + 128];
    }
    __syncthreads();
    float h = b1[tid];
    for (int k = 0; k < DD; k++) h += prow[k] * W1[k * 128 + tid];
    hid[tid] = fmaxf(h, 0.f);
    __syncthreads();
    if (tid < HH) {
        float o = b2[tid];
        for (int k = 0; k < 128; k++) o += hid[k] * W2[k * HH + tid];
        g_gh[side * GG * HH + g * HH + tid] = o;
    }
}

// ---------------- final NTN + scoring ----------------------------------------
__global__ void __launch_bounds__(64) k_score(const float* __restrict__ tnW,
                                              const float* __restrict__ tnV,
                                              const float* __restrict__ tnb,
                                              const float* __restrict__ scW1,
                                              const float* __restrict__ scb1,
                                              const float* __restrict__ scW2,
                                              const float* __restrict__ scb2,
                                              const float* __restrict__ alpha,
                                              float* __restrict__ out) {
    __shared__ float gxs[HH], hxs[HH], t1s[TNW], scs[TNW], hid[TNW];
    __shared__ float l2s;
    int g = blockIdx.x, e = threadIdx.x;
    gxs[e] = g_gh[g * HH + e];
    hxs[e] = g_gh[GG * HH + g * HH + e];
    if (e < TNW) t1s[e] = 0.f;
    if (e == 0) l2s = 0.f;
    __syncthreads();
    float acc[TNW];
    #pragma unroll
    for (int k = 0; k < TNW; k++) acc[k] = 0.f;
    for (int d = 0; d < HH; d++) {
        float gd = gxs[d];
        const float4* wp = (const float4*)(tnW + (d * HH + e) * TNW);
        float4 w0 = wp[0], w1 = wp[1], w2 = wp[2], w3 = wp[3];
        acc[0]  += gd * w0.x; acc[1]  += gd * w0.y; acc[2]  += gd * w0.z; acc[3]  += gd * w0.w;
        acc[4]  += gd * w1.x; acc[5]  += gd * w1.y; acc[6]  += gd * w1.z; acc[7]  += gd * w1.w;
        acc[8]  += gd * w2.x; acc[9]  += gd * w2.y; acc[10] += gd * w2.z; acc[11] += gd * w2.w;
        acc[12] += gd * w3.x; acc[13] += gd * w3.y; acc[14] += gd * w3.z; acc[15] += gd * w3.w;
    }
    float hx = hxs[e];
    #pragma unroll
    for (int k = 0; k < TNW; k++) {
        float s = acc[k] * hx;
        #pragma unroll
        for (int o = 16; o; o >>= 1) s += __shfl_xor_sync(0xffffffffu, s, o);
        if ((e & 31) == 0) atomicAdd(&t1s[k], s);
    }
    float df = gxs[e] - hxs[e];
    float s2 = df * df;
    #pragma unroll
    for (int o = 16; o; o >>= 1) s2 += __shfl_xor_sync(0xffffffffu, s2, o);
    if ((e & 31) == 0) atomicAdd(&l2s, s2);
    __syncthreads();
    if (e < TNW) {
        float t2 = tnb[e];
        for (int j = 0; j < HH; j++) t2 += gxs[j] * tnV[e * 2 * HH + j];
        for (int j = 0; j < HH; j++) t2 += hxs[j] * tnV[e * 2 * HH + HH + j];
        scs[e] = fmaxf(t1s[e] + t2, 0.f);
    }
    __syncthreads();
    if (e < TNW) {
        float h = scb1[e];
        for (int j = 0; j < TNW; j++) h += scs[j] * scW1[j * TNW + e];
        hid[e] = fmaxf(h, 0.f);
    }
    __syncthreads();
    if (e == 0) {
        float sc = scb2[0];
        for (int j = 0; j < TNW; j++) sc += hid[j] * scW2[j];
        float l2 = sqrtf(l2s);
        float al = alpha[0];
        out[g] = al * (1.f / (1.f + expf(-sc))) + (1.f - al) * (1.f / (1.f + expf(l2)));
    }
}

// ---------------- launch ------------------------------------------------------
extern "C" void kernel_launch(void* const* d_in, const int* in_sizes, int n_in,
                              void* d_out, int out_size) {
    const int* ei1    = (const int*)d_in[0];
    const int* ei2    = (const int*)d_in[1];
    const int* bt1    = (const int*)d_in[2];
    const int* bt2    = (const int*)d_in[3];
    const float* ft1  = (const float*)d_in[4];
    const float* ft2  = (const float*)d_in[5];
    const float* preW  = (const float*)d_in[6];
    const float* preb  = (const float*)d_in[7];
    const float* convW = (const float*)d_in[8];
    const float* convb = (const float*)d_in[9];
    const float* delta = (const float*)d_in[10];
    const float* alpha = (const float*)d_in[11];
    const float* mu    = (const float*)d_in[12];
    const float* attW  = (const float*)d_in[13];
    const float* pW1   = (const float*)d_in[14];
    const float* pb1   = (const float*)d_in[15];
    const float* pW2   = (const float*)d_in[16];
    const float* pb2   = (const float*)d_in[17];
    const float* tnW   = (const float*)d_in[18];
    const float* tnV   = (const float*)d_in[19];
    const float* tnb   = (const float*)d_in[20];
    const float* scW1  = (const float*)d_in[21];
    const float* scb1  = (const float*)d_in[22];
    const float* scW2  = (const float*)d_in[23];
    const float* scb2  = (const float*)d_in[24];
    float* out = (float*)d_out;

    k_init<<<dim3(NB, 2), 256>>>(bt1, bt2);
    k_deg<<<dim3(EB, 2), 256>>>(ei1, ei2);
    k_scan1<<<dim3(NB, 2), 256>>>();
    k_scan2<<<2, 512>>>();
    k_scan3<<<dim3(NB, 2), 256>>>();
    k_fill<<<dim3(EB, 2), 256>>>(ei1, ei2);
    k_pre<<<dim3(GB, 2), 256>>>(ft1, ft2, preW, preb, bt1, bt2, delta);
    for (int i = 0; i < 3; i++) {
        k_mm<<<dim3(MMB, 2), 256>>>(convW + i * HH * HH);
        k_gather<<<dim3(GB, 2), 256>>>(convb + i * HH, i);
    }
    k_sumpool<<<dim3(GG, SB, 2), 256>>>();
    k_ctx<<<dim3(GG, 2), 256>>>(attW);
    k_attpool<<<dim3(GG, SB, 2), 256>>>();
    k_mlp<<<dim3(GG, 2), 128>>>(mu, pW1, pb1, pW2, pb2);
    k_score<<<GG, 64>>>(tnW, tnV, tnb, scW1, scb1, scW2, scb2, alpha, out);
}